// round 15
// baseline (speedup 1.0000x reference)
#include <cuda_runtime.h>
#include <math.h>

#define RNK 8
#define DIM 2048
#define BSZ 8
#define SEQ 2048
#define BLOCKS_PER_BATCH 37            /* 8*37 = 296 = 148 SMs * occ 2 */
#define NBLOCKS (BSZ * BLOCKS_PER_BATCH)
#define SCALING 2.0f                   /* 16 / r */

typedef unsigned long long ull;

__device__ __forceinline__ void fma2(ull& acc, ull a, ull b) {
    asm("fma.rn.f32x2 %0, %1, %2, %0;" : "+l"(acc) : "l"(a), "l"(b));
}
__device__ __forceinline__ ull pack2(float s) {
    ull r; unsigned si = __float_as_uint(s);
    asm("mov.b64 %0, {%1, %1};" : "=l"(r) : "r"(si));
    return r;
}
__device__ __forceinline__ float dot4(float4 a, float4 b) {
    return a.x * b.x + a.y * b.y + a.z * b.z + a.w * b.w;
}
__device__ __forceinline__ void cpa16(unsigned dst, const float4* src) {
    asm volatile("cp.async.cg.shared.global [%0], [%1], 16;"
                 :: "r"(dst), "l"(src));
}
__device__ __forceinline__ void cpa_commit() {
    asm volatile("cp.async.commit_group;");
}
__device__ __forceinline__ void cpa_wait1() {
    asm volatile("cp.async.wait_group 1;");
}

// ---- scratch ----
__device__ float g_A[BSZ * RNK * DIM];   // [b][r*DIM+d]
__device__ float g_B[BSZ * RNK * DIM];   // [b][r*DIM+o], pre-scaled by SCALING

// ============================================================
// Kernel 1: gate MLP + adapter build (R14-proven, unchanged).
// ============================================================
__global__ __launch_bounds__(512)
void gate_ab_kernel(const float* __restrict__ ctr,
                    const float* __restrict__ gamma,
                    const float* __restrict__ beta,
                    const float* __restrict__ W1,
                    const float* __restrict__ b1,
                    const float* __restrict__ W2,
                    const float* __restrict__ b2,
                    const float* __restrict__ Wa,
                    const float* __restrict__ Wb) {
    __shared__ float z_s[BSZ][32];
    __shared__ float h_s[BSZ][60];
    __shared__ float gate_s[BSZ][4];

    int warp = threadIdx.x >> 5;
    int lane = threadIdx.x & 31;

    int idx = blockIdx.x * 512 + threadIdx.x;          // [0, 32768)
    int j = idx & (RNK * DIM - 1);
    bool isA = idx < RNK * DIM;
    const float4* Wrow = isA ? (const float4*)Wa : (const float4*)Wb;
    float4 w4 = __ldg(Wrow + j);

    if (warp < BSZ) {
        int w = warp;
        float v = ctr[w * 32 + lane];
        float m = v;
        #pragma unroll
        for (int off = 16; off; off >>= 1) m += __shfl_xor_sync(0xffffffffu, m, off);
        m *= (1.0f / 32.0f);
        float d = v - m;
        float s = d * d;
        #pragma unroll
        for (int off = 16; off; off >>= 1) s += __shfl_xor_sync(0xffffffffu, s, off);
        s *= (1.0f / 32.0f);
        z_s[w][lane] = d * rsqrtf(s + 1e-5f) * gamma[lane] + beta[lane];
        __syncwarp();

        for (int jj = lane; jj < 60; jj += 32) {
            float acc = b1[jj];
            #pragma unroll
            for (int c = 0; c < 32; c++) acc += z_s[w][c] * W1[jj * 32 + c];
            h_s[w][jj] = fmaxf(acc, 0.0f);
        }
        __syncwarp();

        {
            int k = lane & 3;
            float g = b2[k];
            for (int jj = 0; jj < 60; jj++) g += h_s[w][jj] * W2[k * 60 + jj];
            float mx = g;
            #pragma unroll
            for (int off = 1; off < 4; off <<= 1)
                mx = fmaxf(mx, __shfl_xor_sync(0xffffffffu, mx, off));
            float e = __expf(g - mx);
            float sum = e;
            #pragma unroll
            for (int off = 1; off < 4; off <<= 1)
                sum += __shfl_xor_sync(0xffffffffu, sum, off);
            if (lane < 4) gate_s[w][k] = e / sum;
        }
    }
    __syncthreads();

    float* dst = isA ? g_A : g_B;
    float scale = isA ? 1.0f : SCALING;
    #pragma unroll
    for (int b = 0; b < BSZ; b++) {
        float4 g4 = *(const float4*)gate_s[b];
        dst[b * RNK * DIM + j] =
            scale * (w4.x * g4.x + w4.y * g4.y + w4.z * g4.z + w4.w * g4.w);
    }
}

// ============================================================
// Kernel 2: 296 blocks x 512 threads.
//   smem: A half-buffer 32 KB (k 0-7, restaged for k 8-15) +
//         x ring buffer 64 KB (per-warp 2-stage cp.async pipeline).
//   Each lane cp.asyncs & reads back only its own 16 B slots ->
//   wait_group is the only sync needed; lookahead = 1 full k-iter.
// ============================================================
extern __shared__ float As[];   // [8192] A-half + [16384] xbuf = 96 KB

__global__ __launch_bounds__(512, 2)
void main_kernel(const float* __restrict__ x, float* __restrict__ out) {
    __shared__ ull xa2_s[64][RNK];

    int b    = blockIdx.x / BLOCKS_PER_BATCH;
    int slot = blockIdx.x - b * BLOCKS_PER_BATCH;
    int nrows   = (slot < 13) ? 56 : 55;
    int rowbase = (slot < 13) ? slot * 56 : 728 + (slot - 13) * 55;
    int rem = nrows - 48;                       // warps with a 4th row

    int warp = threadIdx.x >> 5;
    int lane = threadIdx.x & 31;

    const float4* Asrc = (const float4*)(g_A + b * RNK * DIM);  // [r][512]
    float4* Asm = (float4*)As;                                   // [r][256]
    float4* xbuf4 = (float4*)(As + RNK * 1024);                  // after 32 KB
    unsigned xb_u32 =
        (unsigned)__cvta_generic_to_shared(As) + RNK * 1024 * 4;

    // ---- stage A half 0 (cols [0,1024) = float4 [0,256) per rank) ----
    for (int i = threadIdx.x; i < 2048; i += 512) {
        int r = i >> 8, c = i & 255;
        Asm[i] = Asrc[r * 512 + c];
    }

    // ---- phase-1 setup + cp.async prologue (2 stages) ----
    bool has4  = warp < rem;
    int wstart = 3 * warp + (has4 ? warp : rem);
    const float4* xw =
        (const float4*)(x + ((size_t)b * SEQ + rowbase + wstart) * DIM);
    const float4* rp0 = xw;
    const float4* rp1 = xw + (DIM / 4);
    const float4* rp2 = xw + 2 * (DIM / 4);
    const float4* rp3 = xw + ((has4 ? 3 : 2) * (DIM / 4));   // phantom = row 2
    int sbase = warp * 2;                     // [warp][stage] slots

    #pragma unroll
    for (int k = 0; k < 2; k++) {
        int d4 = k * 32 + lane;
        unsigned a = xb_u32 + ((((sbase + k) * 4) * 32 + lane) << 4);
        cpa16(a,            rp0 + d4);
        cpa16(a + 512,      rp1 + d4);        // +32 float4
        cpa16(a + 1024,     rp2 + d4);
        cpa16(a + 1536,     rp3 + d4);
        cpa_commit();
    }
    __syncthreads();                          // A half 0 visible

    // ---- phase 1: pipelined k loop ----
    {
        float acc[4][RNK];
        #pragma unroll
        for (int jr = 0; jr < 4; jr++)
            #pragma unroll
            for (int r = 0; r < RNK; r++) acc[jr][r] = 0.0f;

        for (int k = 0; k < 16; k++) {
            if (k == 8) {                     // restage A half 1
                __syncthreads();
                for (int i = threadIdx.x; i < 2048; i += 512) {
                    int r = i >> 8, c = i & 255;
                    Asm[i] = Asrc[r * 512 + 256 + c];
                }
                __syncthreads();
            }
            cpa_wait1();                      // stage k landed
            int st = k & 1;
            int base = ((sbase + st) * 4) * 32 + lane;
            float4 xv0 = xbuf4[base];
            float4 xv1 = xbuf4[base + 32];
            float4 xv2 = xbuf4[base + 64];
            float4 xv3 = xbuf4[base + 96];
            int d4k = (k & 7) * 32 + lane;    // index within A half
            #pragma unroll
            for (int r = 0; r < RNK; r++) {
                float4 a = Asm[r * 256 + d4k];
                acc[0][r] += dot4(xv0, a);
                acc[1][r] += dot4(xv1, a);
                acc[2][r] += dot4(xv2, a);
                acc[3][r] += dot4(xv3, a);
            }
            int kn = k + 2;
            if (kn < 16) {                    // issue stage k+2
                int d4n = kn * 32 + lane;
                unsigned a2 = xb_u32 + ((((sbase + (kn & 1)) * 4) * 32 + lane) << 4);
                cpa16(a2,        rp0 + d4n);
                cpa16(a2 + 512,  rp1 + d4n);
                cpa16(a2 + 1024, rp2 + d4n);
                cpa16(a2 + 1536, rp3 + d4n);
            }
            cpa_commit();                     // empty commits in tail keep counts
        }

        #pragma unroll
        for (int jr = 0; jr < 4; jr++) {
            #pragma unroll
            for (int r = 0; r < RNK; r++) {
                float s = acc[jr][r];
                #pragma unroll
                for (int off = 16; off; off >>= 1)
                    s += __shfl_xor_sync(0xffffffffu, s, off);
                if (lane == 0 && (jr < 3 || has4))
                    xa2_s[wstart + jr][r] = pack2(s);
            }
        }
    }
    __syncthreads();

    // ---- phase 2: thread owns 4 out cols; f32x2; runtime row loop ----
    {
        const float4* Bb4 = (const float4*)(g_B + b * RNK * DIM);
        ull Br0[RNK], Br1[RNK];
        #pragma unroll
        for (int r = 0; r < RNK; r++) {
            float4 bc = __ldg(Bb4 + r * (DIM / 4) + threadIdx.x);
            ulonglong2 p = *(ulonglong2*)&bc;
            Br0[r] = p.x;
            Br1[r] = p.y;
        }

        float4* orow = (float4*)(out + ((size_t)b * SEQ + rowbase) * DIM)
                       + threadIdx.x;
        #pragma unroll 4
        for (int i = 0; i < nrows; i++) {
            ull o0 = 0ull, o1 = 0ull;
            #pragma unroll
            for (int r = 0; r < RNK; r++) {
                ull s2 = xa2_s[i][r];
                fma2(o0, s2, Br0[r]);
                fma2(o1, s2, Br1[r]);
            }
            ulonglong2 ov; ov.x = o0; ov.y = o1;
            __stcs(orow, *(float4*)&ov);
            orow += DIM / 4;
        }
    }
}

// ============================================================
// launcher
// ============================================================
extern "C" void kernel_launch(void* const* d_in, const int* in_sizes, int n_in,
                              void* d_out, int out_size) {
    const float* x     = (const float*)d_in[0];
    const float* ctr   = (const float*)d_in[1];
    const float* gamma = (const float*)d_in[2];
    const float* beta  = (const float*)d_in[3];
    const float* W1    = (const float*)d_in[4];
    const float* b1    = (const float*)d_in[5];
    const float* W2    = (const float*)d_in[6];
    const float* b2    = (const float*)d_in[7];
    const float* Wa    = (const float*)d_in[8];
    const float* Wb    = (const float*)d_in[9];
    float* out = (float*)d_out;

    static bool attr_set = false;
    if (!attr_set) {
        cudaFuncSetAttribute(main_kernel,
                             cudaFuncAttributeMaxDynamicSharedMemorySize,
                             (RNK * 1024 + 16384) * (int)sizeof(float));
        attr_set = true;
    }

    gate_ab_kernel<<<(2 * RNK * DIM) / 512, 512>>>(ctr, gamma, beta,
                                                   W1, b1, W2, b2, Wa, Wb);
    main_kernel<<<NBLOCKS, 512,
                  (RNK * 1024 + 16384) * sizeof(float)>>>(x, out);
}

// round 16
// speedup vs baseline: 1.0916x; 1.0916x over previous
#include <cuda_runtime.h>
#include <math.h>

#define RNK 8
#define DIM 2048
#define BSZ 8
#define SEQ 2048
#define BLOCKS_PER_BATCH 37            /* 8*37 = 296 = 148 SMs * occ 2 */
#define NBLOCKS (BSZ * BLOCKS_PER_BATCH)
#define SCALING 2.0f                   /* 16 / r */

typedef unsigned long long ull;

__device__ __forceinline__ void fma2(ull& acc, ull a, ull b) {
    asm("fma.rn.f32x2 %0, %1, %2, %0;" : "+l"(acc) : "l"(a), "l"(b));
}
__device__ __forceinline__ ull pack2(float s) {
    ull r; unsigned si = __float_as_uint(s);
    asm("mov.b64 %0, {%1, %1};" : "=l"(r) : "r"(si));
    return r;
}
__device__ __forceinline__ float dot4(float4 a, float4 b) {
    return a.x * b.x + a.y * b.y + a.z * b.z + a.w * b.w;
}

// ---- scratch ----
__device__ float g_A[BSZ * RNK * DIM];   // [b][r*DIM+d]
__device__ float g_B[BSZ * RNK * DIM];   // [b][r*DIM+o], pre-scaled by SCALING

// ============================================================
// Kernel 1: gate MLP + adapter build.  64 blocks x 512 threads.
//   Hoisted Wa/Wb load overlaps the gate chain; layer 2 parallelized
//   across 4 lanes (60 FMAs/lane + 4-lane shuffle softmax).
// ============================================================
__global__ __launch_bounds__(512)
void gate_ab_kernel(const float* __restrict__ ctr,
                    const float* __restrict__ gamma,
                    const float* __restrict__ beta,
                    const float* __restrict__ W1,
                    const float* __restrict__ b1,
                    const float* __restrict__ W2,
                    const float* __restrict__ b2,
                    const float* __restrict__ Wa,
                    const float* __restrict__ Wb) {
    __shared__ float z_s[BSZ][32];
    __shared__ float h_s[BSZ][60];
    __shared__ float gate_s[BSZ][4];

    int warp = threadIdx.x >> 5;
    int lane = threadIdx.x & 31;

    // hoisted big load, in flight during the gate chain
    int idx = blockIdx.x * 512 + threadIdx.x;          // [0, 32768)
    int j = idx & (RNK * DIM - 1);
    bool isA = idx < RNK * DIM;
    const float4* Wrow = isA ? (const float4*)Wa : (const float4*)Wb;
    float4 w4 = __ldg(Wrow + j);

    if (warp < BSZ) {
        int w = warp;
        float v = ctr[w * 32 + lane];
        float m = v;
        #pragma unroll
        for (int off = 16; off; off >>= 1) m += __shfl_xor_sync(0xffffffffu, m, off);
        m *= (1.0f / 32.0f);
        float d = v - m;
        float s = d * d;
        #pragma unroll
        for (int off = 16; off; off >>= 1) s += __shfl_xor_sync(0xffffffffu, s, off);
        s *= (1.0f / 32.0f);
        z_s[w][lane] = d * rsqrtf(s + 1e-5f) * gamma[lane] + beta[lane];
        __syncwarp();

        for (int jj = lane; jj < 60; jj += 32) {
            float acc = b1[jj];
            #pragma unroll
            for (int c = 0; c < 32; c++) acc += z_s[w][c] * W1[jj * 32 + c];
            h_s[w][jj] = fmaxf(acc, 0.0f);
        }
        __syncwarp();

        // layer 2: lane k (k<4) computes logit k; softmax via 4-lane shuffles
        {
            int k = lane & 3;
            float g = b2[k];
            for (int jj = 0; jj < 60; jj++) g += h_s[w][jj] * W2[k * 60 + jj];
            float mx = g;
            #pragma unroll
            for (int off = 1; off < 4; off <<= 1)
                mx = fmaxf(mx, __shfl_xor_sync(0xffffffffu, mx, off));
            float e = __expf(g - mx);
            float sum = e;
            #pragma unroll
            for (int off = 1; off < 4; off <<= 1)
                sum += __shfl_xor_sync(0xffffffffu, sum, off);
            if (lane < 4) gate_s[w][k] = e / sum;
        }
    }
    __syncthreads();

    float* dst = isA ? g_A : g_B;
    float scale = isA ? 1.0f : SCALING;
    #pragma unroll
    for (int b = 0; b < BSZ; b++) {
        float4 g4 = *(const float4*)gate_s[b];
        dst[b * RNK * DIM + j] =
            scale * (w4.x * g4.x + w4.y * g4.y + w4.z * g4.z + w4.w * g4.w);
    }
}

// ============================================================
// Kernel 2: 296 blocks (one exact co-resident wave) x 512 threads.
//   block = (batch, 55/56-row tile, never crossing a batch boundary).
//   Phase 1: warps take 3-4 rows, unroll 2, phantom 4th row = own
//   row 2 (L1-hit, discarded).  Phase 2: f32x2, coalesced STG.128.
// ============================================================
extern __shared__ float As[];   // RNK*DIM = 64 KB

__global__ __launch_bounds__(512, 2)
void main_kernel(const float* __restrict__ x, float* __restrict__ out) {
    __shared__ ull xa2_s[64][RNK];

    int b    = blockIdx.x / BLOCKS_PER_BATCH;
    int slot = blockIdx.x - b * BLOCKS_PER_BATCH;
    int nrows   = (slot < 13) ? 56 : 55;
    int rowbase = (slot < 13) ? slot * 56 : 728 + (slot - 13) * 55;
    int rem = nrows - 48;                       // warps with a 4th row

    int warp = threadIdx.x >> 5;
    int lane = threadIdx.x & 31;

    // ---- stage A[b] into smem ----
    {
        const float4* src = (const float4*)(g_A + b * RNK * DIM);
        float4* dst = (float4*)As;
        #pragma unroll
        for (int i = threadIdx.x; i < (RNK * DIM) / 4; i += 512) dst[i] = src[i];
    }
    __syncthreads();

    // ---- phase 1: warp handles 3-4 rows; FFMA dots vs smem A ----
    {
        bool has4  = warp < rem;
        int wstart = 3 * warp + (has4 ? warp : rem);
        const float4* xw =
            (const float4*)(x + ((size_t)b * SEQ + rowbase + wstart) * DIM);
        int off3 = (has4 ? 3 : 2) * (DIM / 4);          // phantom = own row 2
        const float4* As4 = (const float4*)As;

        float acc[4][RNK];
        #pragma unroll
        for (int jr = 0; jr < 4; jr++)
            #pragma unroll
            for (int r = 0; r < RNK; r++) acc[jr][r] = 0.0f;

        #pragma unroll 2
        for (int k = 0; k < 16; k++) {
            int d4 = k * 32 + lane;
            float4 xv0 = __ldcs(xw + 0 * (DIM / 4) + d4);
            float4 xv1 = __ldcs(xw + 1 * (DIM / 4) + d4);
            float4 xv2 = __ldcs(xw + 2 * (DIM / 4) + d4);
            float4 xv3 = __ldcs(xw + off3 + d4);
            #pragma unroll
            for (int r = 0; r < RNK; r++) {
                float4 a = As4[r * 512 + d4];
                acc[0][r] += dot4(xv0, a);
                acc[1][r] += dot4(xv1, a);
                acc[2][r] += dot4(xv2, a);
                acc[3][r] += dot4(xv3, a);
            }
        }
        #pragma unroll
        for (int jr = 0; jr < 4; jr++) {
            #pragma unroll
            for (int r = 0; r < RNK; r++) {
                float s = acc[jr][r];
                #pragma unroll
                for (int off = 16; off; off >>= 1)
                    s += __shfl_xor_sync(0xffffffffu, s, off);
                if (lane == 0 && (jr < 3 || has4))
                    xa2_s[wstart + jr][r] = pack2(s);
            }
        }
    }
    __syncthreads();

    // ---- phase 2: thread owns 4 out cols; f32x2; runtime row loop ----
    {
        const float4* Bb4 = (const float4*)(g_B + b * RNK * DIM);
        ull Br0[RNK], Br1[RNK];
        #pragma unroll
        for (int r = 0; r < RNK; r++) {
            float4 bc = __ldg(Bb4 + r * (DIM / 4) + threadIdx.x);
            ulonglong2 p = *(ulonglong2*)&bc;
            Br0[r] = p.x;
            Br1[r] = p.y;
        }

        float4* orow = (float4*)(out + ((size_t)b * SEQ + rowbase) * DIM)
                       + threadIdx.x;
        #pragma unroll 4
        for (int i = 0; i < nrows; i++) {
            ull o0 = 0ull, o1 = 0ull;
            #pragma unroll
            for (int r = 0; r < RNK; r++) {
                ull s2 = xa2_s[i][r];
                fma2(o0, s2, Br0[r]);
                fma2(o1, s2, Br1[r]);
            }
            ulonglong2 ov; ov.x = o0; ov.y = o1;
            __stcs(orow, *(float4*)&ov);
            orow += DIM / 4;
        }
    }
}

// ============================================================
// launcher
// ============================================================
extern "C" void kernel_launch(void* const* d_in, const int* in_sizes, int n_in,
                              void* d_out, int out_size) {
    const float* x     = (const float*)d_in[0];
    const float* ctr   = (const float*)d_in[1];
    const float* gamma = (const float*)d_in[2];
    const float* beta  = (const float*)d_in[3];
    const float* W1    = (const float*)d_in[4];
    const float* b1    = (const float*)d_in[5];
    const float* W2    = (const float*)d_in[6];
    const float* b2    = (const float*)d_in[7];
    const float* Wa    = (const float*)d_in[8];
    const float* Wb    = (const float*)d_in[9];
    float* out = (float*)d_out;

    static bool attr_set = false;
    if (!attr_set) {
        cudaFuncSetAttribute(main_kernel,
                             cudaFuncAttributeMaxDynamicSharedMemorySize,
                             RNK * DIM * (int)sizeof(float));
        attr_set = true;
    }

    gate_ab_kernel<<<(2 * RNK * DIM) / 512, 512>>>(ctr, gamma, beta,
                                                   W1, b1, W2, b2, Wa, Wb);
    main_kernel<<<NBLOCKS, 512, RNK * DIM * sizeof(float)>>>(x, out);
}